// round 1
// baseline (speedup 1.0000x reference)
#include <cuda_runtime.h>
#include <cuda_bf16.h>
#include <math.h>

#define BB 512
#define NN 2048
#define QDIM 64
#define MDIM 64
#define HH 8
#define KDIM 8
#define VDIM 8
#define ODIM 64
#define HV 64
#define FP16_HUGE 32768.0f

// ---------------- scratch (module-static device memory; no runtime alloc) ----------------
__device__ float g_qavg[BB * QDIM];
__device__ float g_k[(size_t)BB * NN * KDIM];   // 32 MB
__device__ float g_v[(size_t)BB * NN * VDIM];   // 32 MB
__device__ float g_wa[BB * HV];

// ---------------- K1: masked mean of q_data over N (per batch) ----------------
__global__ void k_qavg(const float* __restrict__ q_data, const float* __restrict__ q_mask) {
    int b  = blockIdx.x;
    int c  = threadIdx.x & 63;   // channel
    int ng = threadIdx.x >> 6;   // 0..3 row group
    const float* qb = q_data + (size_t)b * NN * QDIM;
    const float* mb = q_mask + (size_t)b * NN;
    float acc = 0.f, ms = 0.f;
    for (int n = ng; n < NN; n += 4) {
        float m = mb[n];
        acc = fmaf(m, qb[(size_t)n * QDIM + c], acc);
        ms += m;
    }
    __shared__ float sa[4][64];
    __shared__ float sm[4][64];
    sa[ng][c] = acc;
    sm[ng][c] = ms;
    __syncthreads();
    if (ng == 0) {
        float t = sa[0][c] + sa[1][c] + sa[2][c] + sa[3][c];
        float m = sm[0][c] + sm[1][c] + sm[2][c] + sm[3][c];
        g_qavg[b * QDIM + c] = t / (m + 1e-10f);
    }
}

// ---------------- K2: k = m @ key_w, v = m @ value_w ----------------
#define TOK 32
__global__ void k_kv(const float* __restrict__ m_data,
                     const float* __restrict__ key_w,
                     const float* __restrict__ value_w) {
    __shared__ float  msh[TOK][MDIM + 1];
    __shared__ float2 wsh[MDIM][8];   // j<4: key cols {2j,2j+1}; j>=4: value cols
    int tid = threadIdx.x;            // 256
    for (int i = tid; i < MDIM * 8; i += 256) {
        int k = i >> 3, j = i & 7;
        float2 w;
        if (j < 4) w = make_float2(key_w[k * KDIM + 2 * j], key_w[k * KDIM + 2 * j + 1]);
        else       w = make_float2(value_w[k * VDIM + 2 * (j - 4)], value_w[k * VDIM + 2 * (j - 4) + 1]);
        wsh[k][j] = w;
    }
    size_t t0 = (size_t)blockIdx.x * TOK;
    const float4* src = (const float4*)(m_data + t0 * MDIM);
    for (int i = tid; i < TOK * MDIM / 4; i += 256) {
        float4 v = src[i];
        int t = i >> 4, kq = (i & 15) << 2;
        msh[t][kq] = v.x; msh[t][kq + 1] = v.y; msh[t][kq + 2] = v.z; msh[t][kq + 3] = v.w;
    }
    __syncthreads();
    int t = tid >> 3, j = tid & 7;
    float2 acc = make_float2(0.f, 0.f);
#pragma unroll
    for (int k = 0; k < MDIM; k++) {
        float a = msh[t][k];
        float2 w = wsh[k][j];
        acc.x = fmaf(a, w.x, acc.x);
        acc.y = fmaf(a, w.y, acc.y);
    }
    size_t tok = t0 + t;
    if (j < 4) *(float2*)&g_k[tok * KDIM + 2 * j]       = acc;
    else       *(float2*)&g_v[tok * VDIM + 2 * (j - 4)] = acc;
}

// ---------------- K3: per-batch attention -> wa[b, h*8+c] ----------------
__global__ void k_attn(const float* __restrict__ query_w, const float* __restrict__ q_mask) {
    int b = blockIdx.x;
    int tid = threadIdx.x;   // 256
    __shared__ float q_s[64];
    __shared__ float red[9 * 256];
    if (tid < 64) {
        float s = 0.f;
        const float* qa = g_qavg + b * QDIM;
#pragma unroll
        for (int a = 0; a < QDIM; a++) s = fmaf(qa[a], query_w[a * 64 + tid], s);
        q_s[tid] = s * 0.35355339059327373f;   // KD^-0.5
    }
    __syncthreads();
    const float* kb = g_k + (size_t)b * NN * KDIM;
    const float* vb = g_v + (size_t)b * NN * VDIM;
    const float* mb = q_mask + (size_t)b * NN;

    float4 ka[8], ka2[8], va[8], va2[8];
    float mbias[8];
#pragma unroll
    for (int i = 0; i < 8; i++) {
        int n = tid + i * 256;
        ka[i]  = *(const float4*)&kb[(size_t)n * 8];
        ka2[i] = *(const float4*)&kb[(size_t)n * 8 + 4];
        va[i]  = *(const float4*)&vb[(size_t)n * 8];
        va2[i] = *(const float4*)&vb[(size_t)n * 8 + 4];
        mbias[i] = FP16_HUGE * (mb[n] - 1.0f);
    }
    for (int h = 0; h < HH; h++) {
        float q0 = q_s[h * 8 + 0], q1 = q_s[h * 8 + 1], q2 = q_s[h * 8 + 2], q3 = q_s[h * 8 + 3];
        float q4 = q_s[h * 8 + 4], q5 = q_s[h * 8 + 5], q6 = q_s[h * 8 + 6], q7 = q_s[h * 8 + 7];
        float esum = 0.f;
        float w0 = 0, w1 = 0, w2 = 0, w3 = 0, w4 = 0, w5 = 0, w6 = 0, w7 = 0;
#pragma unroll
        for (int i = 0; i < 8; i++) {
            float l = mbias[i];
            l = fmaf(q0, ka[i].x, l);  l = fmaf(q1, ka[i].y, l);
            l = fmaf(q2, ka[i].z, l);  l = fmaf(q3, ka[i].w, l);
            l = fmaf(q4, ka2[i].x, l); l = fmaf(q5, ka2[i].y, l);
            l = fmaf(q6, ka2[i].z, l); l = fmaf(q7, ka2[i].w, l);
            // logits are O(1e-3) here (q_avg ~ 1/sqrt(Nmask)); masked -> -32768 -> exp = 0.
            float e = __expf(l);
            esum += e;
            w0 = fmaf(e, va[i].x, w0);  w1 = fmaf(e, va[i].y, w1);
            w2 = fmaf(e, va[i].z, w2);  w3 = fmaf(e, va[i].w, w3);
            w4 = fmaf(e, va2[i].x, w4); w5 = fmaf(e, va2[i].y, w5);
            w6 = fmaf(e, va2[i].z, w6); w7 = fmaf(e, va2[i].w, w7);
        }
        red[0 * 256 + tid] = esum;
        red[1 * 256 + tid] = w0; red[2 * 256 + tid] = w1;
        red[3 * 256 + tid] = w2; red[4 * 256 + tid] = w3;
        red[5 * 256 + tid] = w4; red[6 * 256 + tid] = w5;
        red[7 * 256 + tid] = w6; red[8 * 256 + tid] = w7;
        __syncthreads();
        for (int s = 128; s > 0; s >>= 1) {
            if (tid < s) {
#pragma unroll
                for (int j = 0; j < 9; j++) red[j * 256 + tid] += red[j * 256 + tid + s];
            }
            __syncthreads();
        }
        if (tid < 8) g_wa[b * 64 + h * 8 + tid] = red[(tid + 1) * 256] / red[0 * 256];
        __syncthreads();
    }
}

// ---------------- K4: gate + output via tf32 tensor cores ----------------
__device__ __forceinline__ unsigned f2tf(float x) {
    unsigned r; asm("cvt.rna.tf32.f32 %0, %1;" : "=r"(r) : "f"(x)); return r;
}

#define QS_STRIDE 68   // conflict-free for A-fragment access pattern
#define WB_STRIDE 72   // conflict-free for B-fragment access pattern
#define SMEM_FLOATS (128 * QS_STRIDE + 64 * WB_STRIDE + 192)

__global__ void k_main(const float* __restrict__ q_data,
                       const float* __restrict__ gating_w,
                       const float* __restrict__ gating_b,
                       const float* __restrict__ output_w,
                       const float* __restrict__ output_b,
                       float* __restrict__ out) {
    extern __shared__ float sh[];
    float* qs   = sh;                         // 128 x 68 (q tile, then gate tile)
    float* wb   = sh + 128 * QS_STRIDE;       // 64 x 72  (gating_w, then wa*output_w)
    float* gb_s = wb + 64 * WB_STRIDE;        // 64
    float* ob_s = gb_s + 64;                  // 64
    float* wa_s = ob_s + 64;                  // 64

    int b    = blockIdx.y;
    int rt   = blockIdx.x;
    int tid  = threadIdx.x;    // 128
    int warp = tid >> 5;
    int lane = tid & 31;
    int g    = lane >> 2;      // 0..7
    int t    = lane & 3;       // 0..3

    if (tid < 64) {
        gb_s[tid] = gating_b[tid];
        ob_s[tid] = output_b[tid];
        wa_s[tid] = g_wa[b * 64 + tid];
    }
    // q tile -> tf32 smem
    const float4* qsrc = (const float4*)(q_data + ((size_t)b * NN + (size_t)rt * 128) * QDIM);
    for (int i = tid; i < 128 * 16; i += 128) {
        float4 v = qsrc[i];
        int r = i >> 4, cq = (i & 15) << 2;
        float* d = qs + r * QS_STRIDE + cq;
        d[0] = __uint_as_float(f2tf(v.x)); d[1] = __uint_as_float(f2tf(v.y));
        d[2] = __uint_as_float(f2tf(v.z)); d[3] = __uint_as_float(f2tf(v.w));
    }
    // gating_w -> tf32 smem (as [k][n])
    for (int i = tid; i < 64 * 16; i += 128) {
        float4 v = ((const float4*)gating_w)[i];
        int k = i >> 4, nq = (i & 15) << 2;
        float* d = wb + k * WB_STRIDE + nq;
        d[0] = __uint_as_float(f2tf(v.x)); d[1] = __uint_as_float(f2tf(v.y));
        d[2] = __uint_as_float(f2tf(v.z)); d[3] = __uint_as_float(f2tf(v.w));
    }
    __syncthreads();

    float c[2][8][4];
#pragma unroll
    for (int mt = 0; mt < 2; mt++)
#pragma unroll
        for (int nt = 0; nt < 8; nt++)
#pragma unroll
            for (int e = 0; e < 4; e++) c[mt][nt][e] = 0.f;

    // ---- mma1: S = Q @ gating_w ----
#pragma unroll
    for (int k8 = 0; k8 < 8; k8++) {
        unsigned a[2][4];
#pragma unroll
        for (int mt = 0; mt < 2; mt++) {
            int r0 = warp * 32 + mt * 16;
            a[mt][0] = __float_as_uint(qs[(r0 + g)     * QS_STRIDE + k8 * 8 + t]);
            a[mt][1] = __float_as_uint(qs[(r0 + g + 8) * QS_STRIDE + k8 * 8 + t]);
            a[mt][2] = __float_as_uint(qs[(r0 + g)     * QS_STRIDE + k8 * 8 + t + 4]);
            a[mt][3] = __float_as_uint(qs[(r0 + g + 8) * QS_STRIDE + k8 * 8 + t + 4]);
        }
#pragma unroll
        for (int nt = 0; nt < 8; nt++) {
            unsigned b0 = __float_as_uint(wb[(k8 * 8 + t)     * WB_STRIDE + nt * 8 + g]);
            unsigned b1 = __float_as_uint(wb[(k8 * 8 + t + 4) * WB_STRIDE + nt * 8 + g]);
#pragma unroll
            for (int mt = 0; mt < 2; mt++) {
                asm volatile(
                    "mma.sync.aligned.m16n8k8.row.col.f32.tf32.tf32.f32 "
                    "{%0,%1,%2,%3}, {%4,%5,%6,%7}, {%8,%9}, {%0,%1,%2,%3};\n"
                    : "+f"(c[mt][nt][0]), "+f"(c[mt][nt][1]), "+f"(c[mt][nt][2]), "+f"(c[mt][nt][3])
                    : "r"(a[mt][0]), "r"(a[mt][1]), "r"(a[mt][2]), "r"(a[mt][3]),
                      "r"(b0), "r"(b1));
            }
        }
    }
    __syncthreads();   // done reading qs (q) and wb (gating_w)

    // ---- sigmoid gate -> qs (tf32) ----
#pragma unroll
    for (int mt = 0; mt < 2; mt++) {
        int r0 = warp * 32 + mt * 16;
#pragma unroll
        for (int nt = 0; nt < 8; nt++) {
            int col = nt * 8 + 2 * t;
            float bb0 = gb_s[col], bb1 = gb_s[col + 1];
            float g0 = 1.f / (1.f + __expf(-(c[mt][nt][0] + bb0)));
            float g1 = 1.f / (1.f + __expf(-(c[mt][nt][1] + bb1)));
            float g2 = 1.f / (1.f + __expf(-(c[mt][nt][2] + bb0)));
            float g3 = 1.f / (1.f + __expf(-(c[mt][nt][3] + bb1)));
            qs[(r0 + g)     * QS_STRIDE + col]     = __uint_as_float(f2tf(g0));
            qs[(r0 + g)     * QS_STRIDE + col + 1] = __uint_as_float(f2tf(g1));
            qs[(r0 + g + 8) * QS_STRIDE + col]     = __uint_as_float(f2tf(g2));
            qs[(r0 + g + 8) * QS_STRIDE + col + 1] = __uint_as_float(f2tf(g3));
        }
    }
    // ---- W2 = wa (.) output_w -> wb (tf32) ----
    for (int i = tid; i < 64 * 16; i += 128) {
        float4 v = ((const float4*)output_w)[i];
        int k = i >> 4, nq = (i & 15) << 2;
        float w = wa_s[k];
        float* d = wb + k * WB_STRIDE + nq;
        d[0] = __uint_as_float(f2tf(w * v.x)); d[1] = __uint_as_float(f2tf(w * v.y));
        d[2] = __uint_as_float(f2tf(w * v.z)); d[3] = __uint_as_float(f2tf(w * v.w));
    }
    __syncthreads();

#pragma unroll
    for (int mt = 0; mt < 2; mt++)
#pragma unroll
        for (int nt = 0; nt < 8; nt++)
#pragma unroll
            for (int e = 0; e < 4; e++) c[mt][nt][e] = 0.f;

    // ---- mma2: out = gate @ W2 ----
#pragma unroll
    for (int k8 = 0; k8 < 8; k8++) {
        unsigned a[2][4];
#pragma unroll
        for (int mt = 0; mt < 2; mt++) {
            int r0 = warp * 32 + mt * 16;
            a[mt][0] = __float_as_uint(qs[(r0 + g)     * QS_STRIDE + k8 * 8 + t]);
            a[mt][1] = __float_as_uint(qs[(r0 + g + 8) * QS_STRIDE + k8 * 8 + t]);
            a[mt][2] = __float_as_uint(qs[(r0 + g)     * QS_STRIDE + k8 * 8 + t + 4]);
            a[mt][3] = __float_as_uint(qs[(r0 + g + 8) * QS_STRIDE + k8 * 8 + t + 4]);
        }
#pragma unroll
        for (int nt = 0; nt < 8; nt++) {
            unsigned b0 = __float_as_uint(wb[(k8 * 8 + t)     * WB_STRIDE + nt * 8 + g]);
            unsigned b1 = __float_as_uint(wb[(k8 * 8 + t + 4) * WB_STRIDE + nt * 8 + g]);
#pragma unroll
            for (int mt = 0; mt < 2; mt++) {
                asm volatile(
                    "mma.sync.aligned.m16n8k8.row.col.f32.tf32.tf32.f32 "
                    "{%0,%1,%2,%3}, {%4,%5,%6,%7}, {%8,%9}, {%0,%1,%2,%3};\n"
                    : "+f"(c[mt][nt][0]), "+f"(c[mt][nt][1]), "+f"(c[mt][nt][2]), "+f"(c[mt][nt][3])
                    : "r"(a[mt][0]), "r"(a[mt][1]), "r"(a[mt][2]), "r"(a[mt][3]),
                      "r"(b0), "r"(b1));
            }
        }
    }

    // ---- epilogue: += output_b, store ----
    float* outp = out + ((size_t)b * NN + (size_t)rt * 128) * ODIM;
#pragma unroll
    for (int mt = 0; mt < 2; mt++) {
        int r0 = warp * 32 + mt * 16 + g;
#pragma unroll
        for (int nt = 0; nt < 8; nt++) {
            int col = nt * 8 + 2 * t;
            float o0 = ob_s[col], o1 = ob_s[col + 1];
            *(float2*)&outp[(size_t)r0 * ODIM + col] =
                make_float2(c[mt][nt][0] + o0, c[mt][nt][1] + o1);
            *(float2*)&outp[(size_t)(r0 + 8) * ODIM + col] =
                make_float2(c[mt][nt][2] + o0, c[mt][nt][3] + o1);
        }
    }
}

// ---------------- launch ----------------
extern "C" void kernel_launch(void* const* d_in, const int* in_sizes, int n_in,
                              void* d_out, int out_size) {
    const float* q_data   = (const float*)d_in[0];
    const float* m_data   = (const float*)d_in[1];
    const float* q_mask   = (const float*)d_in[2];
    // d_in[3] = bias (dummy, unused)
    const float* query_w  = (const float*)d_in[4];
    const float* key_w    = (const float*)d_in[5];
    const float* value_w  = (const float*)d_in[6];
    const float* gating_w = (const float*)d_in[7];
    const float* gating_b = (const float*)d_in[8];
    const float* output_w = (const float*)d_in[9];
    const float* output_b = (const float*)d_in[10];
    float* out = (float*)d_out;

    k_qavg<<<BB, 256>>>(q_data, q_mask);
    k_kv<<<(BB * NN) / TOK, 256>>>(m_data, key_w, value_w);
    k_attn<<<BB, 256>>>(query_w, q_mask);

    int smem = SMEM_FLOATS * 4;   // ~54 KB
    cudaFuncSetAttribute(k_main, cudaFuncAttributeMaxDynamicSharedMemorySize, smem);
    k_main<<<dim3(NN / 128, BB), 128, smem>>>(q_data, gating_w, gating_b,
                                              output_w, output_b, out);
}

// round 3
// speedup vs baseline: 2.2066x; 2.2066x over previous
#include <cuda_runtime.h>
#include <cuda_bf16.h>
#include <math.h>

#define BB 512
#define NN 2048
#define QDIM 64
#define FP16_HUGE 32768.0f

// ---------------- scratch ----------------
__device__ float g_qavg[BB * QDIM];
__device__ float g_wa[BB * 64];

// ---------------- K1: masked mean of q_data over N (per batch) ----------------
__global__ void k_qavg(const float* __restrict__ q_data, const float* __restrict__ q_mask) {
    int b   = blockIdx.x;
    int tid = threadIdx.x;          // 256
    int rg  = tid >> 4;             // 0..15 row group
    int cq  = (tid & 15) << 2;      // channel quad
    const float* qb = q_data + (size_t)b * NN * QDIM;
    const float* mb = q_mask + (size_t)b * NN;
    float4 acc = make_float4(0.f, 0.f, 0.f, 0.f);
    float ms = 0.f;
    for (int n = rg; n < NN; n += 16) {
        float m = mb[n];
        float4 q = *(const float4*)&qb[(size_t)n * QDIM + cq];
        acc.x = fmaf(m, q.x, acc.x); acc.y = fmaf(m, q.y, acc.y);
        acc.z = fmaf(m, q.z, acc.z); acc.w = fmaf(m, q.w, acc.w);
        ms += m;
    }
    __shared__ float4 sa[16][16];
    __shared__ float  sm[16];
    sa[rg][tid & 15] = acc;
    if ((tid & 15) == 0) sm[rg] = ms;
    __syncthreads();
    if (tid < 16) {
        float4 t = make_float4(0.f, 0.f, 0.f, 0.f);
        float msum = 0.f;
#pragma unroll
        for (int r = 0; r < 16; r++) {
            float4 v = sa[r][tid];
            t.x += v.x; t.y += v.y; t.z += v.z; t.w += v.w;
            msum += sm[r];
        }
        float inv = 1.f / (msum + 1e-10f);
        float* dst = g_qavg + b * QDIM + tid * 4;
        dst[0] = t.x * inv; dst[1] = t.y * inv; dst[2] = t.z * inv; dst[3] = t.w * inv;
    }
}

// ---------------- K2: fused attention (no k/v scratch) ----------------
// logits[h][n] = m[n] . qk[:,h],  qk[a][h] = sum_c key_w[a][c] * qh[h][c]
// wa[h][v] = (sum_n e_n m[n]) @ value_w / sum_n e_n
#define MS_STR 68
__global__ void k_attn2(const float* __restrict__ m_data,
                        const float* __restrict__ q_mask,
                        const float* __restrict__ query_w,
                        const float* __restrict__ key_w,
                        const float* __restrict__ value_w) {
    __shared__ __align__(16) float ms[128 * MS_STR];
    __shared__ __align__(16) float es[8 * 132];
    __shared__ __align__(16) float qk_s[512];    // [a][h] : a*8+h
    __shared__ float qh_s[64];
    __shared__ float qa_s[64];
    __shared__ float msk[128];
    __shared__ float wm_s[8 * 68];
    __shared__ float esum_s[8];

    int b   = blockIdx.x;
    int tid = threadIdx.x;   // 256

    if (tid < 64) qa_s[tid] = g_qavg[b * QDIM + tid];
    __syncthreads();
    if (tid < 64) {
        float s = 0.f;
#pragma unroll 16
        for (int d = 0; d < 64; d++) s = fmaf(qa_s[d], query_w[d * 64 + tid], s);
        qh_s[tid] = s * 0.35355339059327373f;   // KD^-0.5
    }
    __syncthreads();
#pragma unroll
    for (int it = 0; it < 2; it++) {
        int i = tid + it * 256;            // 0..511
        int a = i >> 3, h = i & 7;
        float s = 0.f;
#pragma unroll
        for (int c = 0; c < 8; c++) s = fmaf(key_w[a * 8 + c], qh_s[h * 8 + c], s);
        qk_s[a * 8 + h] = s;
    }

    int nloc = tid >> 1;          // token within tile
    int hg   = tid & 1;           // head half (4 heads)
    int h    = tid >> 5;          // warp id = head for wm phase
    int a0   = (tid & 31) << 1;   // channel pair for wm phase

    float wm0 = 0.f, wm1 = 0.f;
    float esr = 0.f;

    const float* mb = q_mask + (size_t)b * NN;

    for (int tile = 0; tile < 16; tile++) {
        __syncthreads();   // previous wm phase done reading ms/es
        const float4* msrc = (const float4*)(m_data + ((size_t)b * NN + tile * 128) * 64);
#pragma unroll
        for (int it = 0; it < 8; it++) {
            int i = tid + it * 256;
            float4 v = msrc[i];
            int r = i >> 4, c = (i & 15) << 2;
            float* d = ms + r * MS_STR + c;
            d[0] = v.x; d[1] = v.y; d[2] = v.z; d[3] = v.w;
        }
        if (tid < 128) msk[tid] = mb[tile * 128 + tid];
        __syncthreads();
        // ---- e phase: each thread computes 4 heads for one token ----
        {
            float4 acc = make_float4(0.f, 0.f, 0.f, 0.f);
            const float* mrow = ms + nloc * MS_STR;
#pragma unroll
            for (int a = 0; a < 64; a += 4) {
                float4 mv = *(const float4*)&mrow[a];
                float4 k0 = *(const float4*)&qk_s[(a + 0) * 8 + hg * 4];
                float4 k1 = *(const float4*)&qk_s[(a + 1) * 8 + hg * 4];
                float4 k2 = *(const float4*)&qk_s[(a + 2) * 8 + hg * 4];
                float4 k3 = *(const float4*)&qk_s[(a + 3) * 8 + hg * 4];
                acc.x = fmaf(mv.x, k0.x, acc.x); acc.y = fmaf(mv.x, k0.y, acc.y);
                acc.z = fmaf(mv.x, k0.z, acc.z); acc.w = fmaf(mv.x, k0.w, acc.w);
                acc.x = fmaf(mv.y, k1.x, acc.x); acc.y = fmaf(mv.y, k1.y, acc.y);
                acc.z = fmaf(mv.y, k1.z, acc.z); acc.w = fmaf(mv.y, k1.w, acc.w);
                acc.x = fmaf(mv.z, k2.x, acc.x); acc.y = fmaf(mv.z, k2.y, acc.y);
                acc.z = fmaf(mv.z, k2.z, acc.z); acc.w = fmaf(mv.z, k2.w, acc.w);
                acc.x = fmaf(mv.w, k3.x, acc.x); acc.y = fmaf(mv.w, k3.y, acc.y);
                acc.z = fmaf(mv.w, k3.z, acc.z); acc.w = fmaf(mv.w, k3.w, acc.w);
            }
            float mbias = FP16_HUGE * (msk[nloc] - 1.0f);
            es[(hg * 4 + 0) * 132 + nloc] = __expf(acc.x + mbias);
            es[(hg * 4 + 1) * 132 + nloc] = __expf(acc.y + mbias);
            es[(hg * 4 + 2) * 132 + nloc] = __expf(acc.z + mbias);
            es[(hg * 4 + 3) * 132 + nloc] = __expf(acc.w + mbias);
        }
        __syncthreads();
        // ---- wm phase: warp h accumulates wm[h][a0..a0+1] over 128 tokens ----
#pragma unroll 8
        for (int n4 = 0; n4 < 128; n4 += 4) {
            float4 e4 = *(const float4*)&es[h * 132 + n4];
            float2 m0 = *(const float2*)&ms[(n4 + 0) * MS_STR + a0];
            float2 m1 = *(const float2*)&ms[(n4 + 1) * MS_STR + a0];
            float2 m2 = *(const float2*)&ms[(n4 + 2) * MS_STR + a0];
            float2 m3 = *(const float2*)&ms[(n4 + 3) * MS_STR + a0];
            wm0 = fmaf(e4.x, m0.x, wm0); wm1 = fmaf(e4.x, m0.y, wm1);
            wm0 = fmaf(e4.y, m1.x, wm0); wm1 = fmaf(e4.y, m1.y, wm1);
            wm0 = fmaf(e4.z, m2.x, wm0); wm1 = fmaf(e4.z, m2.y, wm1);
            wm0 = fmaf(e4.w, m3.x, wm0); wm1 = fmaf(e4.w, m3.y, wm1);
            esr += e4.x + e4.y + e4.z + e4.w;   // identical across lanes of warp
        }
    }
    wm_s[h * 68 + a0] = wm0;
    wm_s[h * 68 + a0 + 1] = wm1;
    if ((tid & 31) == 0) esum_s[h] = esr;
    __syncthreads();
    if (tid < 64) {
        int hh = tid >> 3, v = tid & 7;
        float s = 0.f;
#pragma unroll 16
        for (int a = 0; a < 64; a++) s = fmaf(wm_s[hh * 68 + a], value_w[a * 8 + v], s);
        g_wa[b * 64 + tid] = s / esum_s[hh];
    }
}

// ---------------- K3: gate + output via tf32 mma + ldmatrix ----------------
__device__ __forceinline__ unsigned f2tf(float x) {
    unsigned r; asm("cvt.rna.tf32.f32 %0, %1;" : "=r"(r) : "f"(x)); return r;
}
__device__ __forceinline__ void ldm_x4(unsigned& r0, unsigned& r1, unsigned& r2, unsigned& r3,
                                       unsigned addr) {
    asm volatile("ldmatrix.sync.aligned.m8n8.x4.shared.b16 {%0,%1,%2,%3}, [%4];"
                 : "=r"(r0), "=r"(r1), "=r"(r2), "=r"(r3) : "r"(addr));
}
__device__ __forceinline__ void ldm_x2(unsigned& r0, unsigned& r1, unsigned addr) {
    asm volatile("ldmatrix.sync.aligned.m8n8.x2.shared.b16 {%0,%1}, [%2];"
                 : "=r"(r0), "=r"(r1) : "r"(addr));
}

#define QS_STRIDE 68
#define WB_STRIDE 68
#define SMEM_FLOATS (128 * QS_STRIDE + 64 * WB_STRIDE + 192)

__global__ __launch_bounds__(256, 4)
void k_main(const float* __restrict__ q_data,
            const float* __restrict__ gating_w,
            const float* __restrict__ gating_b,
            const float* __restrict__ output_w,
            const float* __restrict__ output_b,
            float* __restrict__ out) {
    extern __shared__ float sh[];
    float* qs   = sh;                         // 128 x 68 : q tile, then gate tile (tf32)
    float* wb   = sh + 128 * QS_STRIDE;       // 64 x 68  : TRANSPOSED [n][k] weights (tf32)
    float* gb_s = wb + 64 * WB_STRIDE;
    float* ob_s = gb_s + 64;
    float* wa_s = ob_s + 64;

    int b    = blockIdx.y;
    int rt   = blockIdx.x;
    int tid  = threadIdx.x;    // 256
    int warp = tid >> 5;
    int lane = tid & 31;
    int g    = lane >> 2;
    int t    = lane & 3;

    if (tid < 64) {
        gb_s[tid] = gating_b[tid];
        ob_s[tid] = output_b[tid];
        wa_s[tid] = g_wa[b * 64 + tid];
    }
    // q tile -> tf32 smem
    const float4* qsrc = (const float4*)(q_data + ((size_t)b * NN + (size_t)rt * 128) * QDIM);
#pragma unroll
    for (int it = 0; it < 8; it++) {
        int i = tid + it * 256;
        float4 v = qsrc[i];
        int r = i >> 4, c = (i & 15) << 2;
        float* d = qs + r * QS_STRIDE + c;
        d[0] = __uint_as_float(f2tf(v.x)); d[1] = __uint_as_float(f2tf(v.y));
        d[2] = __uint_as_float(f2tf(v.z)); d[3] = __uint_as_float(f2tf(v.w));
    }
    // gating_w (as [k][n]) -> wb transposed [n][k]
#pragma unroll
    for (int it = 0; it < 4; it++) {
        int i = tid + it * 256;
        float4 v = ((const float4*)gating_w)[i];
        int k = i >> 4, nq = (i & 15) << 2;
        wb[(nq + 0) * WB_STRIDE + k] = __uint_as_float(f2tf(v.x));
        wb[(nq + 1) * WB_STRIDE + k] = __uint_as_float(f2tf(v.y));
        wb[(nq + 2) * WB_STRIDE + k] = __uint_as_float(f2tf(v.z));
        wb[(nq + 3) * WB_STRIDE + k] = __uint_as_float(f2tf(v.w));
    }
    __syncthreads();

    // ldmatrix lane address bases
    unsigned qs_base = (unsigned)__cvta_generic_to_shared(qs);
    unsigned wb_base = (unsigned)__cvta_generic_to_shared(wb);
    int mi = lane >> 3;
    unsigned a_row  = warp * 16 + (lane & 7) + (mi & 1) * 8;
    unsigned a_off  = qs_base + (a_row * QS_STRIDE + (mi >> 1) * 4) * 4;
    int lb = lane & 15;
    unsigned b_term = wb_base + ((lb & 7) * WB_STRIDE + (lb >> 3) * 4) * 4;

    float c_[8][4];
#pragma unroll
    for (int nt = 0; nt < 8; nt++)
#pragma unroll
        for (int e = 0; e < 4; e++) c_[nt][e] = 0.f;

    // ---- mma1: S = Q @ Gw ----
#pragma unroll
    for (int k8 = 0; k8 < 8; k8++) {
        unsigned a0, a1, a2, a3;
        ldm_x4(a0, a1, a2, a3, a_off + k8 * 32);
#pragma unroll
        for (int nt = 0; nt < 8; nt++) {
            unsigned b0, b1;
            ldm_x2(b0, b1, b_term + (unsigned)(nt * 8 * WB_STRIDE * 4 + k8 * 32));
            asm volatile(
                "mma.sync.aligned.m16n8k8.row.col.f32.tf32.tf32.f32 "
                "{%0,%1,%2,%3}, {%4,%5,%6,%7}, {%8,%9}, {%0,%1,%2,%3};\n"
                : "+f"(c_[nt][0]), "+f"(c_[nt][1]), "+f"(c_[nt][2]), "+f"(c_[nt][3])
                : "r"(a0), "r"(a1), "r"(a2), "r"(a3), "r"(b0), "r"(b1));
        }
    }

    // ---- sigmoid gate -> qs rows (warp-private rows, tf32) ----
    {
        int r0 = warp * 16;
#pragma unroll
        for (int nt = 0; nt < 8; nt++) {
            int col = nt * 8 + 2 * t;
            float bb0 = gb_s[col], bb1 = gb_s[col + 1];
            float g0 = 1.f / (1.f + __expf(-(c_[nt][0] + bb0)));
            float g1 = 1.f / (1.f + __expf(-(c_[nt][1] + bb1)));
            float g2 = 1.f / (1.f + __expf(-(c_[nt][2] + bb0)));
            float g3 = 1.f / (1.f + __expf(-(c_[nt][3] + bb1)));
            qs[(r0 + g)     * QS_STRIDE + col]     = __uint_as_float(f2tf(g0));
            qs[(r0 + g)     * QS_STRIDE + col + 1] = __uint_as_float(f2tf(g1));
            qs[(r0 + 8 + g) * QS_STRIDE + col]     = __uint_as_float(f2tf(g2));
            qs[(r0 + 8 + g) * QS_STRIDE + col + 1] = __uint_as_float(f2tf(g3));
        }
    }
    __syncthreads();   // everyone done reading wb (Gw)
    // ---- W2 = wa (.) output_w -> wb transposed [n][k] ----
#pragma unroll
    for (int it = 0; it < 4; it++) {
        int i = tid + it * 256;
        float4 v = ((const float4*)output_w)[i];
        int k = i >> 4, nq = (i & 15) << 2;
        float w = wa_s[k];
        wb[(nq + 0) * WB_STRIDE + k] = __uint_as_float(f2tf(w * v.x));
        wb[(nq + 1) * WB_STRIDE + k] = __uint_as_float(f2tf(w * v.y));
        wb[(nq + 2) * WB_STRIDE + k] = __uint_as_float(f2tf(w * v.z));
        wb[(nq + 3) * WB_STRIDE + k] = __uint_as_float(f2tf(w * v.w));
    }
    __syncthreads();

#pragma unroll
    for (int nt = 0; nt < 8; nt++)
#pragma unroll
        for (int e = 0; e < 4; e++) c_[nt][e] = 0.f;

    // ---- mma2: out = gate @ W2 ----
#pragma unroll
    for (int k8 = 0; k8 < 8; k8++) {
        unsigned a0, a1, a2, a3;
        ldm_x4(a0, a1, a2, a3, a_off + k8 * 32);
#pragma unroll
        for (int nt = 0; nt < 8; nt++) {
            unsigned b0, b1;
            ldm_x2(b0, b1, b_term + (unsigned)(nt * 8 * WB_STRIDE * 4 + k8 * 32));
            asm volatile(
                "mma.sync.aligned.m16n8k8.row.col.f32.tf32.tf32.f32 "
                "{%0,%1,%2,%3}, {%4,%5,%6,%7}, {%8,%9}, {%0,%1,%2,%3};\n"
                : "+f"(c_[nt][0]), "+f"(c_[nt][1]), "+f"(c_[nt][2]), "+f"(c_[nt][3])
                : "r"(a0), "r"(a1), "r"(a2), "r"(a3), "r"(b0), "r"(b1));
        }
    }

    // ---- epilogue ----
    float* outp = out + ((size_t)b * NN + (size_t)rt * 128) * 64;
    int r0 = warp * 16 + g;
#pragma unroll
    for (int nt = 0; nt < 8; nt++) {
        int col = nt * 8 + 2 * t;
        float o0 = ob_s[col], o1 = ob_s[col + 1];
        *(float2*)&outp[(size_t)r0 * 64 + col] =
            make_float2(c_[nt][0] + o0, c_[nt][1] + o1);
        *(float2*)&outp[(size_t)(r0 + 8) * 64 + col] =
            make_float2(c_[nt][2] + o0, c_[nt][3] + o1);
    }
}

// ---------------- launch ----------------
extern "C" void kernel_launch(void* const* d_in, const int* in_sizes, int n_in,
                              void* d_out, int out_size) {
    const float* q_data   = (const float*)d_in[0];
    const float* m_data   = (const float*)d_in[1];
    const float* q_mask   = (const float*)d_in[2];
    const float* query_w  = (const float*)d_in[4];
    const float* key_w    = (const float*)d_in[5];
    const float* value_w  = (const float*)d_in[6];
    const float* gating_w = (const float*)d_in[7];
    const float* gating_b = (const float*)d_in[8];
    const float* output_w = (const float*)d_in[9];
    const float* output_b = (const float*)d_in[10];
    float* out = (float*)d_out;

    k_qavg<<<BB, 256>>>(q_data, q_mask);
    k_attn2<<<BB, 256>>>(m_data, q_mask, query_w, key_w, value_w);

    int smem = SMEM_FLOATS * 4;
    cudaFuncSetAttribute(k_main, cudaFuncAttributeMaxDynamicSharedMemorySize, smem);
    k_main<<<dim3(NN / 128, BB), 256, smem>>>(q_data, gating_w, gating_b,
                                              output_w, output_b, out);
}

// round 5
// speedup vs baseline: 2.2666x; 1.0272x over previous
#include <cuda_runtime.h>
#include <cuda_bf16.h>
#include <math.h>

#define BB 512
#define NN 2048
#define QDIM 64
#define FP16_HUGE 32768.0f

// ---------------- scratch ----------------
__device__ float g_qsum[BB * 2 * 64];    // partial masked sums (2 halves per batch)
__device__ float g_msum[BB * 2];
__device__ float g_wmp[BB * 4 * 8 * 64]; // partial wm per chunk
__device__ float g_esp[BB * 4 * 8];      // partial esum per chunk
__device__ float g_wa[BB * 64];

// ---------------- K1: partial masked sum of q_data (2 CTAs per batch) ----------------
__global__ void k_qavg(const float* __restrict__ q_data, const float* __restrict__ q_mask) {
    int b    = blockIdx.x >> 1;
    int half = blockIdx.x & 1;
    int tid  = threadIdx.x;          // 256
    int rg   = tid >> 4;             // 0..15 row group
    int cq   = (tid & 15) << 2;      // channel quad
    int n0   = half * 1024;
    const float* qb = q_data + (size_t)b * NN * QDIM;
    const float* mb = q_mask + (size_t)b * NN;
    float4 acc = make_float4(0.f, 0.f, 0.f, 0.f);
    float ms = 0.f;
#pragma unroll 4
    for (int n = n0 + rg; n < n0 + 1024; n += 32) {
        float m0 = mb[n];
        float m1 = mb[n + 16];
        float4 a = *(const float4*)&qb[(size_t)n * QDIM + cq];
        float4 c = *(const float4*)&qb[(size_t)(n + 16) * QDIM + cq];
        acc.x = fmaf(m0, a.x, acc.x); acc.y = fmaf(m0, a.y, acc.y);
        acc.z = fmaf(m0, a.z, acc.z); acc.w = fmaf(m0, a.w, acc.w);
        acc.x = fmaf(m1, c.x, acc.x); acc.y = fmaf(m1, c.y, acc.y);
        acc.z = fmaf(m1, c.z, acc.z); acc.w = fmaf(m1, c.w, acc.w);
        ms += m0 + m1;
    }
    __shared__ float4 sa[16][16];
    __shared__ float  sm[16];
    sa[rg][tid & 15] = acc;
    if ((tid & 15) == 0) sm[rg] = ms;
    __syncthreads();
    if (tid < 16) {
        float4 t = make_float4(0.f, 0.f, 0.f, 0.f);
        float msum = 0.f;
#pragma unroll
        for (int r = 0; r < 16; r++) {
            float4 v = sa[r][tid];
            t.x += v.x; t.y += v.y; t.z += v.z; t.w += v.w;
            msum += sm[r];
        }
        float* dst = g_qsum + (b * 2 + half) * 64 + tid * 4;
        dst[0] = t.x; dst[1] = t.y; dst[2] = t.z; dst[3] = t.w;
        if (tid == 0) g_msum[b * 2 + half] = msum;
    }
}

// ---------------- K2: fused attention, 4 chunks per batch ----------------
// logits[h][n] = m[n] . qk[:,h],  qk[a][h] = sum_c key_w[a][c] * qh[h][c]
// partial wm[h][a] = sum_{n in chunk} e_n m[n][a];  partial esum[h]
#define MS_STR 68
__global__ void k_attn2(const float* __restrict__ m_data,
                        const float* __restrict__ q_mask,
                        const float* __restrict__ query_w,
                        const float* __restrict__ key_w) {
    __shared__ __align__(16) float ms[128 * MS_STR];
    __shared__ __align__(16) float es[8 * 132];
    __shared__ __align__(16) float qk_s[512];    // [a][h]
    __shared__ float qh_s[64];
    __shared__ float qa_s[64];
    __shared__ float msk[128];

    int b     = blockIdx.x >> 2;
    int chunk = blockIdx.x & 3;
    int tid   = threadIdx.x;   // 256

    if (tid < 64) {
        float msum = g_msum[b * 2] + g_msum[b * 2 + 1];
        qa_s[tid] = (g_qsum[b * 128 + tid] + g_qsum[b * 128 + 64 + tid]) / (msum + 1e-10f);
    }
    __syncthreads();
    if (tid < 64) {
        float s = 0.f;
#pragma unroll 16
        for (int d = 0; d < 64; d++) s = fmaf(qa_s[d], query_w[d * 64 + tid], s);
        qh_s[tid] = s * 0.35355339059327373f;   // KD^-0.5
    }
    __syncthreads();
#pragma unroll
    for (int it = 0; it < 2; it++) {
        int i = tid + it * 256;
        int a = i >> 3, h = i & 7;
        float s = 0.f;
#pragma unroll
        for (int c = 0; c < 8; c++) s = fmaf(key_w[a * 8 + c], qh_s[h * 8 + c], s);
        qk_s[a * 8 + h] = s;
    }

    int nloc = tid >> 1;          // token within tile
    int hg   = tid & 1;           // head half
    int h    = tid >> 5;          // warp id = head for wm phase
    int a0   = (tid & 31) << 1;   // channel pair for wm phase

    float wm0 = 0.f, wm1 = 0.f;
    float esr = 0.f;

    const float* mb = q_mask + (size_t)b * NN;

    for (int tile = chunk * 4; tile < chunk * 4 + 4; tile++) {
        __syncthreads();
        const float4* msrc = (const float4*)(m_data + ((size_t)b * NN + tile * 128) * 64);
#pragma unroll
        for (int it = 0; it < 8; it++) {
            int i = tid + it * 256;
            float4 v = msrc[i];
            int r = i >> 4, c = (i & 15) << 2;
            float* d = ms + r * MS_STR + c;
            d[0] = v.x; d[1] = v.y; d[2] = v.z; d[3] = v.w;
        }
        if (tid < 128) msk[tid] = mb[tile * 128 + tid];
        __syncthreads();
        // ---- e phase ----
        {
            float4 acc = make_float4(0.f, 0.f, 0.f, 0.f);
            const float* mrow = ms + nloc * MS_STR;
#pragma unroll
            for (int a = 0; a < 64; a += 4) {
                float4 mv = *(const float4*)&mrow[a];
                float4 k0 = *(const float4*)&qk_s[(a + 0) * 8 + hg * 4];
                float4 k1 = *(const float4*)&qk_s[(a + 1) * 8 + hg * 4];
                float4 k2 = *(const float4*)&qk_s[(a + 2) * 8 + hg * 4];
                float4 k3 = *(const float4*)&qk_s[(a + 3) * 8 + hg * 4];
                acc.x = fmaf(mv.x, k0.x, acc.x); acc.y = fmaf(mv.x, k0.y, acc.y);
                acc.z = fmaf(mv.x, k0.z, acc.z); acc.w = fmaf(mv.x, k0.w, acc.w);
                acc.x = fmaf(mv.y, k1.x, acc.x); acc.y = fmaf(mv.y, k1.y, acc.y);
                acc.z = fmaf(mv.y, k1.z, acc.z); acc.w = fmaf(mv.y, k1.w, acc.w);
                acc.x = fmaf(mv.z, k2.x, acc.x); acc.y = fmaf(mv.z, k2.y, acc.y);
                acc.z = fmaf(mv.z, k2.z, acc.z); acc.w = fmaf(mv.z, k2.w, acc.w);
                acc.x = fmaf(mv.w, k3.x, acc.x); acc.y = fmaf(mv.w, k3.y, acc.y);
                acc.z = fmaf(mv.w, k3.z, acc.z); acc.w = fmaf(mv.w, k3.w, acc.w);
            }
            float mbias = FP16_HUGE * (msk[nloc] - 1.0f);
            es[(hg * 4 + 0) * 132 + nloc] = __expf(acc.x + mbias);
            es[(hg * 4 + 1) * 132 + nloc] = __expf(acc.y + mbias);
            es[(hg * 4 + 2) * 132 + nloc] = __expf(acc.z + mbias);
            es[(hg * 4 + 3) * 132 + nloc] = __expf(acc.w + mbias);
        }
        __syncthreads();
        // ---- wm phase: warp h accumulates wm[h][a0..a0+1] ----
#pragma unroll 8
        for (int n4 = 0; n4 < 128; n4 += 4) {
            float4 e4 = *(const float4*)&es[h * 132 + n4];
            float2 m0 = *(const float2*)&ms[(n4 + 0) * MS_STR + a0];
            float2 m1 = *(const float2*)&ms[(n4 + 1) * MS_STR + a0];
            float2 m2 = *(const float2*)&ms[(n4 + 2) * MS_STR + a0];
            float2 m3 = *(const float2*)&ms[(n4 + 3) * MS_STR + a0];
            wm0 = fmaf(e4.x, m0.x, wm0); wm1 = fmaf(e4.x, m0.y, wm1);
            wm0 = fmaf(e4.y, m1.x, wm0); wm1 = fmaf(e4.y, m1.y, wm1);
            wm0 = fmaf(e4.z, m2.x, wm0); wm1 = fmaf(e4.z, m2.y, wm1);
            wm0 = fmaf(e4.w, m3.x, wm0); wm1 = fmaf(e4.w, m3.y, wm1);
            esr += e4.x + e4.y + e4.z + e4.w;
        }
    }
    float* wmp = g_wmp + ((size_t)(b * 4 + chunk) * 8 + h) * 64;
    wmp[a0] = wm0;
    wmp[a0 + 1] = wm1;
    if ((tid & 31) == 0) g_esp[(b * 4 + chunk) * 8 + h] = esr;
}

// ---------------- K2b: finalize wa = (sum_chunks wm) @ value_w / esum ----------------
__global__ void k_wafin(const float* __restrict__ value_w) {
    __shared__ float wm_s[8 * 65];
    __shared__ float es_s[8];
    int b = blockIdx.x;
    int tid = threadIdx.x;   // 64
    for (int i = tid; i < 512; i += 64) {
        const float* p = g_wmp + (size_t)b * 4 * 512 + i;
        float s = p[0] + p[512] + p[1024] + p[1536];
        wm_s[(i >> 6) * 65 + (i & 63)] = s;
    }
    if (tid < 8) {
        const float* p = g_esp + b * 32 + tid;
        es_s[tid] = p[0] + p[8] + p[16] + p[24];
    }
    __syncthreads();
    int h = tid >> 3, v = tid & 7;
    float s = 0.f;
#pragma unroll 16
    for (int a = 0; a < 64; a++) s = fmaf(wm_s[h * 65 + a], value_w[a * 8 + v], s);
    g_wa[b * 64 + tid] = s / es_s[h];
}

// ---------------- K3: gate + output via tf32 mma + ldmatrix ----------------
__device__ __forceinline__ unsigned f2tf(float x) {
    unsigned r; asm("cvt.rna.tf32.f32 %0, %1;" : "=r"(r) : "f"(x)); return r;
}
__device__ __forceinline__ void ldm_x4(unsigned& r0, unsigned& r1, unsigned& r2, unsigned& r3,
                                       unsigned addr) {
    asm volatile("ldmatrix.sync.aligned.m8n8.x4.shared.b16 {%0,%1,%2,%3}, [%4];"
                 : "=r"(r0), "=r"(r1), "=r"(r2), "=r"(r3) : "r"(addr));
}
__device__ __forceinline__ void ldm_x2(unsigned& r0, unsigned& r1, unsigned addr) {
    asm volatile("ldmatrix.sync.aligned.m8n8.x2.shared.b16 {%0,%1}, [%2];"
                 : "=r"(r0), "=r"(r1) : "r"(addr));
}

#define QS_STRIDE 68
#define WB_STRIDE 68
#define SMEM_FLOATS (128 * QS_STRIDE + 64 * WB_STRIDE + 192)

__global__ __launch_bounds__(256, 4)
void k_main(const float* __restrict__ q_data,
            const float* __restrict__ gating_w,
            const float* __restrict__ gating_b,
            const float* __restrict__ output_w,
            const float* __restrict__ output_b,
            float* __restrict__ out) {
    extern __shared__ float sh[];
    float* qs   = sh;
    float* wb   = sh + 128 * QS_STRIDE;
    float* gb_s = wb + 64 * WB_STRIDE;
    float* ob_s = gb_s + 64;
    float* wa_s = ob_s + 64;

    int b    = blockIdx.y;
    int rt   = blockIdx.x;
    int tid  = threadIdx.x;    // 256
    int warp = tid >> 5;
    int lane = tid & 31;
    int g    = lane >> 2;
    int t    = lane & 3;

    if (tid < 64) {
        gb_s[tid] = gating_b[tid];
        ob_s[tid] = output_b[tid];
        wa_s[tid] = g_wa[b * 64 + tid];
    }
    const float4* qsrc = (const float4*)(q_data + ((size_t)b * NN + (size_t)rt * 128) * QDIM);
#pragma unroll
    for (int it = 0; it < 8; it++) {
        int i = tid + it * 256;
        float4 v = qsrc[i];
        int r = i >> 4, c = (i & 15) << 2;
        float* d = qs + r * QS_STRIDE + c;
        d[0] = __uint_as_float(f2tf(v.x)); d[1] = __uint_as_float(f2tf(v.y));
        d[2] = __uint_as_float(f2tf(v.z)); d[3] = __uint_as_float(f2tf(v.w));
    }
#pragma unroll
    for (int it = 0; it < 4; it++) {
        int i = tid + it * 256;
        float4 v = ((const float4*)gating_w)[i];
        int k = i >> 4, nq = (i & 15) << 2;
        wb[(nq + 0) * WB_STRIDE + k] = __uint_as_float(f2tf(v.x));
        wb[(nq + 1) * WB_STRIDE + k] = __uint_as_float(f2tf(v.y));
        wb[(nq + 2) * WB_STRIDE + k] = __uint_as_float(f2tf(v.z));
        wb[(nq + 3) * WB_STRIDE + k] = __uint_as_float(f2tf(v.w));
    }
    __syncthreads();

    unsigned qs_base = (unsigned)__cvta_generic_to_shared(qs);
    unsigned wb_base = (unsigned)__cvta_generic_to_shared(wb);
    int mi = lane >> 3;
    unsigned a_row  = warp * 16 + (lane & 7) + (mi & 1) * 8;
    unsigned a_off  = qs_base + (a_row * QS_STRIDE + (mi >> 1) * 4) * 4;
    int lb = lane & 15;
    unsigned b_term = wb_base + ((lb & 7) * WB_STRIDE + (lb >> 3) * 4) * 4;

    float c_[8][4];
#pragma unroll
    for (int nt = 0; nt < 8; nt++)
#pragma unroll
        for (int e = 0; e < 4; e++) c_[nt][e] = 0.f;

    // ---- mma1: S = Q @ Gw ----
#pragma unroll
    for (int k8 = 0; k8 < 8; k8++) {
        unsigned a0, a1, a2, a3;
        ldm_x4(a0, a1, a2, a3, a_off + k8 * 32);
#pragma unroll
        for (int nt = 0; nt < 8; nt++) {
            unsigned b0, b1;
            ldm_x2(b0, b1, b_term + (unsigned)(nt * 8 * WB_STRIDE * 4 + k8 * 32));
            asm volatile(
                "mma.sync.aligned.m16n8k8.row.col.f32.tf32.tf32.f32 "
                "{%0,%1,%2,%3}, {%4,%5,%6,%7}, {%8,%9}, {%0,%1,%2,%3};\n"
                : "+f"(c_[nt][0]), "+f"(c_[nt][1]), "+f"(c_[nt][2]), "+f"(c_[nt][3])
                : "r"(a0), "r"(a1), "r"(a2), "r"(a3), "r"(b0), "r"(b1));
        }
    }

    // ---- sigmoid gate -> qs (tf32) ----
    {
        int r0 = warp * 16;
#pragma unroll
        for (int nt = 0; nt < 8; nt++) {
            int col = nt * 8 + 2 * t;
            float bb0 = gb_s[col], bb1 = gb_s[col + 1];
            float g0 = 1.f / (1.f + __expf(-(c_[nt][0] + bb0)));
            float g1 = 1.f / (1.f + __expf(-(c_[nt][1] + bb1)));
            float g2 = 1.f / (1.f + __expf(-(c_[nt][2] + bb0)));
            float g3 = 1.f / (1.f + __expf(-(c_[nt][3] + bb1)));
            qs[(r0 + g)     * QS_STRIDE + col]     = __uint_as_float(f2tf(g0));
            qs[(r0 + g)     * QS_STRIDE + col + 1] = __uint_as_float(f2tf(g1));
            qs[(r0 + 8 + g) * QS_STRIDE + col]     = __uint_as_float(f2tf(g2));
            qs[(r0 + 8 + g) * QS_STRIDE + col + 1] = __uint_as_float(f2tf(g3));
        }
    }
    __syncthreads();
    // ---- W2 = wa (.) output_w -> wb transposed ----
#pragma unroll
    for (int it = 0; it < 4; it++) {
        int i = tid + it * 256;
        float4 v = ((const float4*)output_w)[i];
        int k = i >> 4, nq = (i & 15) << 2;
        float w = wa_s[k];
        wb[(nq + 0) * WB_STRIDE + k] = __uint_as_float(f2tf(w * v.x));
        wb[(nq + 1) * WB_STRIDE + k] = __uint_as_float(f2tf(w * v.y));
        wb[(nq + 2) * WB_STRIDE + k] = __uint_as_float(f2tf(w * v.z));
        wb[(nq + 3) * WB_STRIDE + k] = __uint_as_float(f2tf(w * v.w));
    }
    __syncthreads();

#pragma unroll
    for (int nt = 0; nt < 8; nt++)
#pragma unroll
        for (int e = 0; e < 4; e++) c_[nt][e] = 0.f;

    // ---- mma2: out = gate @ W2 ----
#pragma unroll
    for (int k8 = 0; k8 < 8; k8++) {
        unsigned a0, a1, a2, a3;
        ldm_x4(a0, a1, a2, a3, a_off + k8 * 32);
#pragma unroll
        for (int nt = 0; nt < 8; nt++) {
            unsigned b0, b1;
            ldm_x2(b0, b1, b_term + (unsigned)(nt * 8 * WB_STRIDE * 4 + k8 * 32));
            asm volatile(
                "mma.sync.aligned.m16n8k8.row.col.f32.tf32.tf32.f32 "
                "{%0,%1,%2,%3}, {%4,%5,%6,%7}, {%8,%9}, {%0,%1,%2,%3};\n"
                : "+f"(c_[nt][0]), "+f"(c_[nt][1]), "+f"(c_[nt][2]), "+f"(c_[nt][3])
                : "r"(a0), "r"(a1), "r"(a2), "r"(a3), "r"(b0), "r"(b1));
        }
    }

    // ---- epilogue ----
    float* outp = out + ((size_t)b * NN + (size_t)rt * 128) * 64;
    int r0 = warp * 16 + g;
#pragma unroll
    for (int nt = 0; nt < 8; nt++) {
        int col = nt * 8 + 2 * t;
        float o0 = ob_s[col], o1 = ob_s[col + 1];
        *(float2*)&outp[(size_t)r0 * 64 + col] =
            make_float2(c_[nt][0] + o0, c_[nt][1] + o1);
        *(float2*)&outp[(size_t)(r0 + 8) * 64 + col] =
            make_float2(c_[nt][2] + o0, c_[nt][3] + o1);
    }
}

// ---------------- launch ----------------
extern "C" void kernel_launch(void* const* d_in, const int* in_sizes, int n_in,
                              void* d_out, int out_size) {
    const float* q_data   = (const float*)d_in[0];
    const float* m_data   = (const float*)d_in[1];
    const float* q_mask   = (const float*)d_in[2];
    const float* query_w  = (const float*)d_in[4];
    const float* key_w    = (const float*)d_in[5];
    const float* value_w  = (const float*)d_in[6];
    const float* gating_w = (const float*)d_in[7];
    const float* gating_b = (const float*)d_in[8];
    const float* output_w = (const float*)d_in[9];
    const float* output_b = (const float*)d_in[10];
    float* out = (float*)d_out;

    k_qavg<<<BB * 2, 256>>>(q_data, q_mask);
    k_attn2<<<BB * 4, 256>>>(m_data, q_mask, query_w, key_w);
    k_wafin<<<BB, 64>>>(value_w);

    int smem = SMEM_FLOATS * 4;
    cudaFuncSetAttribute(k_main, cudaFuncAttributeMaxDynamicSharedMemorySize, smem);
    k_main<<<dim3(NN / 128, BB), 256, smem>>>(q_data, gating_w, gating_b,
                                              output_w, output_b, out);
}